// round 14
// baseline (speedup 1.0000x reference)
#include <cuda_runtime.h>
#include <cuda_fp16.h>
#include <cstdint>

#define NB   16
#define SEQ  1024
#define DIM  512
#define NH   8
#define DH   64

// Scratch (allocation-free __device__ globals)
__device__ uint4 g_Q4 [(size_t)NB*NH*SEQ*DH/8];   // Q fp16 [b,h,i,d] (pre-scaled 0.125*log2e)
__device__ uint4 g_K4 [(size_t)NB*NH*SEQ*DH/8];   // K fp16 [b,h,i,d]
__device__ uint4 g_V4 [(size_t)NB*NH*SEQ*DH/8];   // V fp16 [b,h,i,d]
__device__ uint4 g_AO4[(size_t)NB*SEQ*DIM/8];     // attn out fp16
__device__ uint4 g_X4 [(size_t)NB*SEQ*DIM/8];     // x fp16
__device__ uint4 g_W4 [(size_t)4*DIM*DIM/8];      // Wq|Wk|Wv|Wo fp16
// bias fp16 * log2e, permuted (see prep fused kernel)
__device__ uint4 g_B2 [(size_t)NH*SEQ*SEQ/8];

#define LOG2E 1.4426950408889634f

__device__ __forceinline__ uint32_t pack2(float a, float b) {
    __half2 h = __floats2half2_rn(a, b);
    return *(uint32_t*)&h;
}

__device__ __forceinline__ void mma16(float c[4], uint32_t a0, uint32_t a1,
                                      uint32_t a2, uint32_t a3,
                                      uint32_t b0, uint32_t b1) {
    asm volatile(
        "mma.sync.aligned.m16n8k16.row.col.f32.f16.f16.f32 "
        "{%0,%1,%2,%3}, {%4,%5,%6,%7}, {%8,%9}, {%0,%1,%2,%3};"
        : "+f"(c[0]), "+f"(c[1]), "+f"(c[2]), "+f"(c[3])
        : "r"(a0), "r"(a1), "r"(a2), "r"(a3), "r"(b0), "r"(b1));
}

__device__ __forceinline__ void ldm4(uint32_t& r0, uint32_t& r1, uint32_t& r2,
                                     uint32_t& r3, uint32_t addr) {
    asm volatile("ldmatrix.sync.aligned.m8n8.x4.shared.b16 {%0,%1,%2,%3}, [%4];"
                 : "=r"(r0), "=r"(r1), "=r"(r2), "=r"(r3) : "r"(addr));
}
__device__ __forceinline__ void ldm4t(uint32_t& r0, uint32_t& r1, uint32_t& r2,
                                      uint32_t& r3, uint32_t addr) {
    asm volatile("ldmatrix.sync.aligned.m8n8.x4.trans.shared.b16 {%0,%1,%2,%3}, [%4];"
                 : "=r"(r0), "=r"(r1), "=r"(r2), "=r"(r3) : "r"(addr));
}

__device__ __forceinline__ void cp16(uint32_t dst, const void* src) {
    asm volatile("cp.async.cg.shared.global [%0], [%1], 16;" :: "r"(dst), "l"(src));
}

__device__ __forceinline__ uint32_t hexp2_2(uint32_t a) {
    uint32_t r;
    asm("ex2.approx.f16x2 %0, %1;" : "=r"(r) : "r"(a));
    return r;
}

// ---------------------------------------------------------------------------
// Fused prep: fp32 -> fp16 for x / W / bias (one launch).
// ---------------------------------------------------------------------------
__global__ void __launch_bounds__(256) prep_all(
    const float* __restrict__ X,  const float* __restrict__ B,
    const float* __restrict__ Wq, const float* __restrict__ Wk,
    const float* __restrict__ Wv, const float* __restrict__ Wo)
{
    const int bx = blockIdx.x;
    if (bx < 4096) {
        const size_t i = ((size_t)bx*256 + threadIdx.x) * 8;
        const float4 f0 = *(const float4*)&X[i];
        const float4 f1 = *(const float4*)&X[i+4];
        g_X4[i >> 3] = make_uint4(pack2(f0.x, f0.y), pack2(f0.z, f0.w),
                                  pack2(f1.x, f1.y), pack2(f1.z, f1.w));
    } else if (bx < 4608) {
        const size_t i = ((size_t)(bx-4096)*256 + threadIdx.x) * 8;
        const int w = (int)(i >> 18);
        const float* __restrict__ src = (w==0)?Wq:(w==1)?Wk:(w==2)?Wv:Wo;
        const size_t p = i & ((1u << 18) - 1);
        const float4 f0 = *(const float4*)&src[p];
        const float4 f1 = *(const float4*)&src[p+4];
        g_W4[i >> 3] = make_uint4(pack2(f0.x, f0.y), pack2(f0.z, f0.w),
                                  pack2(f1.x, f1.y), pack2(f1.z, f1.w));
    } else {
        const size_t t = (size_t)(bx-4608)*256 + threadIdx.x;   // 0 .. 1M-1
        const size_t L = t * 8;
        const int R   = (int)(L >> 11);
        const int o   = (int)(L & 2047);
        const int h   = R >> 9;
        const int rem = R & 511;
        const int i16 = rem >> 3, l = rem & 7;
        const int bi  = i16*16 + l;
        const float* __restrict__ Bh = B + ((size_t)h << 20);

        uint32_t out[4];
        #pragma unroll
        for (int g2 = 0; g2 < 2; g2++) {
            const int j = ((o >> 2) + g2) * 2;
            const float2 f0 = *(const float2*)&Bh[(size_t)bi*SEQ + j];
            const float2 f1 = *(const float2*)&Bh[(size_t)(bi+8)*SEQ + j];
            out[g2*2 + 0] = pack2(f0.x*LOG2E, f0.y*LOG2E);
            out[g2*2 + 1] = pack2(f1.x*LOG2E, f1.y*LOG2E);
        }
        g_B2[t] = make_uint4(out[0], out[1], out[2], out[3]);
    }
}

// ---------------------------------------------------------------------------
// GEMM (qkv + oproj): Y = A @ W^T, fp16 in, fp32 accum, mma.sync.
// BM=128, BN=128, BK=64; 128 threads = 4 warps (2m x 2n), warp tile 64x64.
// A-fragments register-double-buffered across ks: ks+1's ldm4s issue BEFORE
// the ks mma burst, so mmas only ever wait on the interleaved B ldm.
// smem pitch 72 halfs; A[2] @ 0/18432, B[2] @ 36864/55296 = 73,728 B.
// ---------------------------------------------------------------------------
__global__ void __launch_bounds__(128) mm_kernel(float* __restrict__ outp, int op)
{
    extern __shared__ __align__(1024) unsigned char smraw[];
    const uint32_t smem_b = (uint32_t)__cvta_generic_to_shared(smraw);

    const int z = op ? 3 : blockIdx.z;
    const __half* __restrict__ At = op ? (const __half*)g_AO4 : (const __half*)g_X4;
    const __half* __restrict__ Bt = (const __half*)g_W4 + (size_t)z*DIM*DIM;

    const int tid  = threadIdx.x;
    const int lane = tid & 31, warp = tid >> 5;
    const int q    = lane & 3, l4 = lane >> 2;
    const int g    = lane >> 3, r8 = lane & 7;
    const int wm   = warp >> 1, wn = warp & 1;
    const int m0   = blockIdx.y << 7;
    const int c0   = blockIdx.x << 7;

    const uint32_t aoff = ((wm*64 + (g&1)*8 + r8)*72 + (g>>1)*8) * 2;
    const uint32_t boff = ((wn*64 + (g>>1)*8 + r8)*72 + (g&1)*8) * 2;

    auto stage = [&](int k0, int buf) {
        #pragma unroll
        for (int t = 0; t < 16; t++) {
            const int f = tid + t*128;
            const int r = (f >> 3) & 127;
            const int j = f & 7;
            const uint32_t dst = smem_b + ((f & 1024) ? 36864 : 0) + buf*18432
                               + r*144 + j*16;
            const __half* src = ((f & 1024) ? Bt + (size_t)(c0+r)*DIM
                                            : At + (size_t)(m0+r)*DIM) + k0 + j*8;
            cp16(dst, src);
        }
        asm volatile("cp.async.commit_group;");
    };

    float acc[4][8][4] = {};
    stage(0, 0);

    for (int kt = 0; kt < 8; kt++) {
        asm volatile("cp.async.wait_group 0;");
        __syncthreads();
        if (kt < 7) stage((kt+1)*64, (kt+1) & 1);

        const uint32_t As_b = smem_b + (kt & 1)*18432;
        const uint32_t Bs_b = smem_b + 36864 + (kt & 1)*18432;

        uint32_t a[2][4][4];
        #pragma unroll
        for (int mt = 0; mt < 4; mt++)
            ldm4(a[0][mt][0], a[0][mt][1], a[0][mt][2], a[0][mt][3],
                 As_b + aoff + mt*2304);

        #pragma unroll
        for (int ks = 0; ks < 4; ks++) {
            const int cur = ks & 1;
            if (ks < 3) {
                #pragma unroll
                for (int mt = 0; mt < 4; mt++)
                    ldm4(a[cur^1][mt][0], a[cur^1][mt][1],
                         a[cur^1][mt][2], a[cur^1][mt][3],
                         As_b + aoff + mt*2304 + (ks+1)*32);
            }
            #pragma unroll
            for (int p = 0; p < 4; p++) {
                uint32_t b0, b1, b2, b3;
                ldm4(b0, b1, b2, b3, Bs_b + boff + p*2304 + ks*32);
                #pragma unroll
                for (int mt = 0; mt < 4; mt++) {
                    mma16(acc[mt][2*p],   a[cur][mt][0], a[cur][mt][1],
                          a[cur][mt][2], a[cur][mt][3], b0, b1);
                    mma16(acc[mt][2*p+1], a[cur][mt][0], a[cur][mt][1],
                          a[cur][mt][2], a[cur][mt][3], b2, b3);
                }
            }
        }
    }

    if (op) {
        #pragma unroll
        for (int mt = 0; mt < 4; mt++)
            #pragma unroll
            for (int half = 0; half < 2; half++) {
                const int m = m0 + wm*64 + mt*16 + half*8 + l4;
                #pragma unroll
                for (int nt = 0; nt < 8; nt++) {
                    const int col = c0 + wn*64 + nt*8 + 2*q;
                    *(float2*)&outp[(size_t)m*DIM + col] =
                        make_float2(acc[mt][nt][half*2], acc[mt][nt][half*2+1]);
                }
            }
    } else {
        __half* __restrict__ Y = (__half*)((z==0) ? g_Q4 : (z==1) ? g_K4 : g_V4);
        const float scale = (z == 0) ? 0.125f * LOG2E : 1.0f;
        #pragma unroll
        for (int mt = 0; mt < 4; mt++)
            #pragma unroll
            for (int half = 0; half < 2; half++) {
                const int m  = m0 + wm*64 + mt*16 + half*8 + l4;
                const int bb = m >> 10, i = m & (SEQ-1);
                #pragma unroll
                for (int nt = 0; nt < 8; nt++) {
                    const int col = c0 + wn*64 + nt*8 + 2*q;
                    const int h = col >> 6, d = col & 63;
                    const size_t base = ((size_t)(bb*NH + h)*SEQ + i)*DH + d;
                    *(uint32_t*)&Y[base] = pack2(acc[mt][nt][half*2]   * scale,
                                                 acc[mt][nt][half*2+1] * scale);
                }
            }
    }
}

// ---------------------------------------------------------------------------
// Flash attention, fp16 mma.  256 thr = 8 warps x 16 q-rows.
// KV tiles of 128 keys (8 outer iters, two 64-key sub-tiles each), double-
// buffered cp.async -> half the syncthreads/wait rounds of the 64-key loop.
// Bias fp16 pre-scaled/permuted, per-warp stripe (pitch 560B, bank-clean).
// P = exp2(fp32 s + fp32 bias) packed once -> ex2.approx.f16x2; row sums via
// ones-mma.  smem: K[2][128x144B] | V[2][128x144B] | bias 8x4480 = 109,568 B.
// ---------------------------------------------------------------------------
__global__ void __launch_bounds__(256, 2) attn_kernel(const float* __restrict__ bias_unused)
{
    extern __shared__ __align__(1024) unsigned char smatt[];
    const uint32_t smem_b = (uint32_t)__cvta_generic_to_shared(smatt);

    const int tid  = threadIdx.x;
    const int lane = tid & 31, warp = tid >> 5;
    const int q    = lane & 3, l4 = lane >> 2;
    const int g    = lane >> 3, r8 = lane & 7;
    const int b    = blockIdx.z, h = blockIdx.y;
    const int i0   = blockIdx.x << 7;
    const int W0   = warp << 4;

    const __half* __restrict__ Qg = (const __half*)g_Q4 + ((size_t)(b*NH + h)*SEQ + i0)*DH;
    const __half* __restrict__ Kg = (const __half*)g_K4 + (size_t)(b*NH + h)*SEQ*DH;
    const __half* __restrict__ Vg = (const __half*)g_V4 + (size_t)(b*NH + h)*SEQ*DH;
    const int i16g = (i0 >> 4) + warp;
    const __half* __restrict__ B2h = (const __half*)g_B2 + ((size_t)(h*64 + i16g) * 8) * 2048;

    const uint32_t koff = (((g>>1)*8 + r8)*72 + (g&1)*8) * 2;   // K non-trans
    const uint32_t voff = (((g&1)*8 + r8)*72 + (g>>1)*8) * 2;   // V trans
    const uint32_t bias_sm = smem_b + 73728 + warp*4480;        // own stripe

    // stage 128 rows of K and V (18432 B each)
    auto stage_kv = [&](int j0, int buf) {
        #pragma unroll
        for (int t = 0; t < 4; t++) {
            const int f = tid + t*256;                // 0..1023
            const int row = f >> 3, cB = (f & 7) * 16;
            cp16(smem_b + buf*18432 + row*144 + cB,         Kg + (size_t)(j0+row)*DH + cB/2);
            cp16(smem_b + 36864 + buf*18432 + row*144 + cB, Vg + (size_t)(j0+row)*DH + cB/2);
        }
        asm volatile("cp.async.commit_group;");
    };
    // per-warp stripe: 8 l-rows x 512B data, pitch 560B
    auto stage_bias = [&](int j0) {
        #pragma unroll
        for (int t = 0; t < 8; t++) {
            const int u = lane + 32*t;                // 0..255
            const int l = u >> 5, cB = (u & 31) * 16;
            cp16(bias_sm + l*560 + cB, B2h + (size_t)l*2048 + j0*2 + cB/2);
        }
        asm volatile("cp.async.commit_group;");
    };

    stage_kv(0, 0);
    stage_bias(0);

    // Q a-frags -> registers (one-time)
    const uint32_t* Qu = (const uint32_t*)Qg;
    uint32_t qf[4][4];
    #pragma unroll
    for (int ks = 0; ks < 4; ks++) {
        const int r = W0 + l4;
        qf[ks][0] = Qu[(size_t)r*32     + ks*8 + q];
        qf[ks][1] = Qu[(size_t)(r+8)*32 + ks*8 + q];
        qf[ks][2] = Qu[(size_t)r*32     + ks*8 + 4 + q];
        qf[ks][3] = Qu[(size_t)(r+8)*32 + ks*8 + 4 + q];
    }

    float o[8][4] = {};
    float lpacc[4] = {};
    const uint32_t ONES = 0x3C003C00u;

    for (int it = 0; it < 8; it++) {
        const int j0  = it << 7;
        const int buf = it & 1;

        asm volatile("cp.async.wait_group 1;");   // KV_it resident (bias_it may fly)
        __syncthreads();                          // readers of buf^1 done

        if (it < 7) stage_kv(j0 + 128, buf ^ 1);

        #pragma unroll
        for (int sub = 0; sub < 2; sub++) {
            const uint32_t ksb = smem_b + buf*18432 + sub*9216;
            const uint32_t vsb = smem_b + 36864 + buf*18432 + sub*9216;

            // S = Q K^T  (exp2-domain)
            float s[8][4] = {};
            #pragma unroll
            for (int ks = 0; ks < 4; ks++) {
                #pragma unroll
                for (int p = 0; p < 4; p++) {
                    uint32_t b0, b1, b2, b3;
                    ldm4(b0, b1, b2, b3, ksb + koff + p*2304 + ks*32);
                    mma16(s[2*p],   qf[ks][0], qf[ks][1], qf[ks][2], qf[ks][3], b0, b1);
                    mma16(s[2*p+1], qf[ks][0], qf[ks][1], qf[ks][2], qf[ks][3], b2, b3);
                }
            }

            // bias wait only once per outer iter (before first use)
            if (sub == 0) {
                if (it < 7) { asm volatile("cp.async.wait_group 1;"); }
                else        { asm volatile("cp.async.wait_group 0;"); }
            }

            // P = exp2(s + bias): fp32 add, pack once, f16x2 exp
            uint32_t ph0[8], ph1[8];
            #pragma unroll
            for (int nt = 0; nt < 8; nt++) {
                const uint2 bh = *(const uint2*)(smatt + 73728 + warp*4480
                                                 + l4*560 + sub*256 + nt*32 + q*8);
                const float2 bf0 = __half22float2(*(const __half2*)&bh.x);
                const float2 bf1 = __half22float2(*(const __half2*)&bh.y);
                ph0[nt] = hexp2_2(pack2(s[nt][0] + bf0.x, s[nt][1] + bf0.y));
                ph1[nt] = hexp2_2(pack2(s[nt][2] + bf1.x, s[nt][3] + bf1.y));
            }

            // row sums via ones-mma
            #pragma unroll
            for (int ks = 0; ks < 4; ks++)
                mma16(lpacc, ph0[2*ks], ph1[2*ks], ph0[2*ks+1], ph1[2*ks+1], ONES, ONES);

            // O += P @ V
            #pragma unroll
            for (int ks = 0; ks < 4; ks++) {
                #pragma unroll
                for (int p = 0; p < 4; p++) {
                    uint32_t b0, b1, b2, b3;
                    ldm4t(b0, b1, b2, b3, vsb + voff + ks*2304 + p*32);
                    mma16(o[2*p],   ph0[2*ks], ph1[2*ks], ph0[2*ks+1], ph1[2*ks+1], b0, b1);
                    mma16(o[2*p+1], ph0[2*ks], ph1[2*ks], ph0[2*ks+1], ph1[2*ks+1], b2, b3);
                }
            }
        }

        if (it < 7) stage_bias(j0 + 128);
    }

    const float inv0 = 1.f / lpacc[0];
    const float inv1 = 1.f / lpacc[2];

    __half* __restrict__ AOh = (__half*)g_AO4;
    const int gi = i0 + W0 + l4;
    #pragma unroll
    for (int nt = 0; nt < 8; nt++) {
        const int d = nt*8 + 2*q;
        const size_t b0 = ((size_t)b*SEQ + gi)*DIM + h*DH + d;
        const size_t b1 = ((size_t)b*SEQ + gi + 8)*DIM + h*DH + d;
        *(uint32_t*)&AOh[b0] = pack2(o[nt][0]*inv0, o[nt][1]*inv0);
        *(uint32_t*)&AOh[b1] = pack2(o[nt][2]*inv1, o[nt][3]*inv1);
    }
}

// ---------------------------------------------------------------------------
extern "C" void kernel_launch(void* const* d_in, const int* in_sizes, int n_in,
                              void* d_out, int out_size)
{
    const float* x    = (const float*)d_in[0];
    const float* bias = (const float*)d_in[1];
    const float* Wq   = (const float*)d_in[2];
    const float* Wk   = (const float*)d_in[3];
    const float* Wv   = (const float*)d_in[4];
    const float* Wo   = (const float*)d_in[5];
    float* out = (float*)d_out;

    prep_all<<<8704, 256>>>(x, bias, Wq, Wk, Wv, Wo);

    const int mm_smem = 73728;   // A[2] 2x18432 | B[2] 2x18432
    cudaFuncSetAttribute(mm_kernel, cudaFuncAttributeMaxDynamicSharedMemorySize, mm_smem);
    mm_kernel<<<dim3(DIM/128, (NB*SEQ)/128, 3), 128, mm_smem>>>(nullptr, 0);

    const int at_smem = 109568;  // K 2x18432 | V 2x18432 | bias 8x4480
    cudaFuncSetAttribute(attn_kernel, cudaFuncAttributeMaxDynamicSharedMemorySize, at_smem);
    attn_kernel<<<dim3(SEQ/128, NH, NB), 256, at_smem>>>(bias);

    mm_kernel<<<dim3(DIM/128, (NB*SEQ)/128, 1), 128, mm_smem>>>(out, 1);
}

// round 15
// speedup vs baseline: 1.0167x; 1.0167x over previous
#include <cuda_runtime.h>
#include <cuda_fp16.h>
#include <cstdint>

#define NB   16
#define SEQ  1024
#define DIM  512
#define NH   8
#define DH   64

// Scratch (allocation-free __device__ globals)
__device__ uint4 g_Q4 [(size_t)NB*NH*SEQ*DH/8];   // Q fp16 [b,h,i,d] (pre-scaled 0.125*log2e)
__device__ uint4 g_K4 [(size_t)NB*NH*SEQ*DH/8];   // K fp16 [b,h,i,d]
__device__ uint4 g_V4 [(size_t)NB*NH*SEQ*DH/8];   // V fp16 [b,h,i,d]
__device__ uint4 g_AO4[(size_t)NB*SEQ*DIM/8];     // attn out fp16
__device__ uint4 g_X4 [(size_t)NB*SEQ*DIM/8];     // x fp16
__device__ uint4 g_W4 [(size_t)4*DIM*DIM/8];      // Wq|Wk|Wv|Wo fp16
// bias fp16 * log2e, permuted (see prep fused kernel)
__device__ uint4 g_B2 [(size_t)NH*SEQ*SEQ/8];

#define LOG2E 1.4426950408889634f

__device__ __forceinline__ uint32_t pack2(float a, float b) {
    __half2 h = __floats2half2_rn(a, b);
    return *(uint32_t*)&h;
}

__device__ __forceinline__ void mma16(float c[4], uint32_t a0, uint32_t a1,
                                      uint32_t a2, uint32_t a3,
                                      uint32_t b0, uint32_t b1) {
    asm volatile(
        "mma.sync.aligned.m16n8k16.row.col.f32.f16.f16.f32 "
        "{%0,%1,%2,%3}, {%4,%5,%6,%7}, {%8,%9}, {%0,%1,%2,%3};"
        : "+f"(c[0]), "+f"(c[1]), "+f"(c[2]), "+f"(c[3])
        : "r"(a0), "r"(a1), "r"(a2), "r"(a3), "r"(b0), "r"(b1));
}

__device__ __forceinline__ void ldm4(uint32_t& r0, uint32_t& r1, uint32_t& r2,
                                     uint32_t& r3, uint32_t addr) {
    asm volatile("ldmatrix.sync.aligned.m8n8.x4.shared.b16 {%0,%1,%2,%3}, [%4];"
                 : "=r"(r0), "=r"(r1), "=r"(r2), "=r"(r3) : "r"(addr));
}
__device__ __forceinline__ void ldm4t(uint32_t& r0, uint32_t& r1, uint32_t& r2,
                                      uint32_t& r3, uint32_t addr) {
    asm volatile("ldmatrix.sync.aligned.m8n8.x4.trans.shared.b16 {%0,%1,%2,%3}, [%4];"
                 : "=r"(r0), "=r"(r1), "=r"(r2), "=r"(r3) : "r"(addr));
}

__device__ __forceinline__ void cp16(uint32_t dst, const void* src) {
    asm volatile("cp.async.cg.shared.global [%0], [%1], 16;" :: "r"(dst), "l"(src));
}

__device__ __forceinline__ uint32_t hexp2_2(uint32_t a) {
    uint32_t r;
    asm("ex2.approx.f16x2 %0, %1;" : "=r"(r) : "r"(a));
    return r;
}

// ---------------------------------------------------------------------------
// Fused prep: fp32 -> fp16 for x / W / bias (one launch).
// ---------------------------------------------------------------------------
__global__ void __launch_bounds__(256) prep_all(
    const float* __restrict__ X,  const float* __restrict__ B,
    const float* __restrict__ Wq, const float* __restrict__ Wk,
    const float* __restrict__ Wv, const float* __restrict__ Wo)
{
    const int bx = blockIdx.x;
    if (bx < 4096) {
        const size_t i = ((size_t)bx*256 + threadIdx.x) * 8;
        const float4 f0 = *(const float4*)&X[i];
        const float4 f1 = *(const float4*)&X[i+4];
        g_X4[i >> 3] = make_uint4(pack2(f0.x, f0.y), pack2(f0.z, f0.w),
                                  pack2(f1.x, f1.y), pack2(f1.z, f1.w));
    } else if (bx < 4608) {
        const size_t i = ((size_t)(bx-4096)*256 + threadIdx.x) * 8;
        const int w = (int)(i >> 18);
        const float* __restrict__ src = (w==0)?Wq:(w==1)?Wk:(w==2)?Wv:Wo;
        const size_t p = i & ((1u << 18) - 1);
        const float4 f0 = *(const float4*)&src[p];
        const float4 f1 = *(const float4*)&src[p+4];
        g_W4[i >> 3] = make_uint4(pack2(f0.x, f0.y), pack2(f0.z, f0.w),
                                  pack2(f1.x, f1.y), pack2(f1.z, f1.w));
    } else {
        const size_t t = (size_t)(bx-4608)*256 + threadIdx.x;   // 0 .. 1M-1
        const size_t L = t * 8;
        const int R   = (int)(L >> 11);
        const int o   = (int)(L & 2047);
        const int h   = R >> 9;
        const int rem = R & 511;
        const int i16 = rem >> 3, l = rem & 7;
        const int bi  = i16*16 + l;
        const float* __restrict__ Bh = B + ((size_t)h << 20);

        uint32_t out[4];
        #pragma unroll
        for (int g2 = 0; g2 < 2; g2++) {
            const int j = ((o >> 2) + g2) * 2;
            const float2 f0 = *(const float2*)&Bh[(size_t)bi*SEQ + j];
            const float2 f1 = *(const float2*)&Bh[(size_t)(bi+8)*SEQ + j];
            out[g2*2 + 0] = pack2(f0.x*LOG2E, f0.y*LOG2E);
            out[g2*2 + 1] = pack2(f1.x*LOG2E, f1.y*LOG2E);
        }
        g_B2[t] = make_uint4(out[0], out[1], out[2], out[3]);
    }
}

// ---------------------------------------------------------------------------
// GEMM (qkv + oproj): unchanged from R13/R14 (36us oproj, ~23us/GEMM).
// ---------------------------------------------------------------------------
__global__ void __launch_bounds__(128) mm_kernel(float* __restrict__ outp, int op)
{
    extern __shared__ __align__(1024) unsigned char smraw[];
    const uint32_t smem_b = (uint32_t)__cvta_generic_to_shared(smraw);

    const int z = op ? 3 : blockIdx.z;
    const __half* __restrict__ At = op ? (const __half*)g_AO4 : (const __half*)g_X4;
    const __half* __restrict__ Bt = (const __half*)g_W4 + (size_t)z*DIM*DIM;

    const int tid  = threadIdx.x;
    const int lane = tid & 31, warp = tid >> 5;
    const int q    = lane & 3, l4 = lane >> 2;
    const int g    = lane >> 3, r8 = lane & 7;
    const int wm   = warp >> 1, wn = warp & 1;
    const int m0   = blockIdx.y << 7;
    const int c0   = blockIdx.x << 7;

    const uint32_t aoff = ((wm*64 + (g&1)*8 + r8)*72 + (g>>1)*8) * 2;
    const uint32_t boff = ((wn*64 + (g>>1)*8 + r8)*72 + (g&1)*8) * 2;

    auto stage = [&](int k0, int buf) {
        #pragma unroll
        for (int t = 0; t < 16; t++) {
            const int f = tid + t*128;
            const int r = (f >> 3) & 127;
            const int j = f & 7;
            const uint32_t dst = smem_b + ((f & 1024) ? 36864 : 0) + buf*18432
                               + r*144 + j*16;
            const __half* src = ((f & 1024) ? Bt + (size_t)(c0+r)*DIM
                                            : At + (size_t)(m0+r)*DIM) + k0 + j*8;
            cp16(dst, src);
        }
        asm volatile("cp.async.commit_group;");
    };

    float acc[4][8][4] = {};
    stage(0, 0);

    for (int kt = 0; kt < 8; kt++) {
        asm volatile("cp.async.wait_group 0;");
        __syncthreads();
        if (kt < 7) stage((kt+1)*64, (kt+1) & 1);

        const uint32_t As_b = smem_b + (kt & 1)*18432;
        const uint32_t Bs_b = smem_b + 36864 + (kt & 1)*18432;

        uint32_t a[2][4][4];
        #pragma unroll
        for (int mt = 0; mt < 4; mt++)
            ldm4(a[0][mt][0], a[0][mt][1], a[0][mt][2], a[0][mt][3],
                 As_b + aoff + mt*2304);

        #pragma unroll
        for (int ks = 0; ks < 4; ks++) {
            const int cur = ks & 1;
            if (ks < 3) {
                #pragma unroll
                for (int mt = 0; mt < 4; mt++)
                    ldm4(a[cur^1][mt][0], a[cur^1][mt][1],
                         a[cur^1][mt][2], a[cur^1][mt][3],
                         As_b + aoff + mt*2304 + (ks+1)*32);
            }
            #pragma unroll
            for (int p = 0; p < 4; p++) {
                uint32_t b0, b1, b2, b3;
                ldm4(b0, b1, b2, b3, Bs_b + boff + p*2304 + ks*32);
                #pragma unroll
                for (int mt = 0; mt < 4; mt++) {
                    mma16(acc[mt][2*p],   a[cur][mt][0], a[cur][mt][1],
                          a[cur][mt][2], a[cur][mt][3], b0, b1);
                    mma16(acc[mt][2*p+1], a[cur][mt][0], a[cur][mt][1],
                          a[cur][mt][2], a[cur][mt][3], b2, b3);
                }
            }
        }
    }

    if (op) {
        #pragma unroll
        for (int mt = 0; mt < 4; mt++)
            #pragma unroll
            for (int half = 0; half < 2; half++) {
                const int m = m0 + wm*64 + mt*16 + half*8 + l4;
                #pragma unroll
                for (int nt = 0; nt < 8; nt++) {
                    const int col = c0 + wn*64 + nt*8 + 2*q;
                    *(float2*)&outp[(size_t)m*DIM + col] =
                        make_float2(acc[mt][nt][half*2], acc[mt][nt][half*2+1]);
                }
            }
    } else {
        __half* __restrict__ Y = (__half*)((z==0) ? g_Q4 : (z==1) ? g_K4 : g_V4);
        const float scale = (z == 0) ? 0.125f * LOG2E : 1.0f;
        #pragma unroll
        for (int mt = 0; mt < 4; mt++)
            #pragma unroll
            for (int half = 0; half < 2; half++) {
                const int m  = m0 + wm*64 + mt*16 + half*8 + l4;
                const int bb = m >> 10, i = m & (SEQ-1);
                #pragma unroll
                for (int nt = 0; nt < 8; nt++) {
                    const int col = c0 + wn*64 + nt*8 + 2*q;
                    const int h = col >> 6, d = col & 63;
                    const size_t base = ((size_t)(bb*NH + h)*SEQ + i)*DH + d;
                    *(uint32_t*)&Y[base] = pack2(acc[mt][nt][half*2]   * scale,
                                                 acc[mt][nt][half*2+1] * scale);
                }
            }
    }
}

// ---------------------------------------------------------------------------
// Flash attention, fp16 mma.  128 thr = 4 WARPS x 32 q-rows (two m16 frags):
// K/V ldmatrix duplication drops 8x -> 4x (each ldm4 feeds 4 mmas), halving
// the CTA's LDSM wavefront traffic -- the binding L1 resource at R13.
// KV tiles of 128 keys (two 64-key sub-tiles), double-buffered cp.async.
// Bias fp16 pre-scaled/permuted, per-warp 16-row stripe (pitch 560B).
// P = exp2(fp32 s + fp32 bias) packed once -> ex2.approx.f16x2; row sums via
// ones-mma.  smem: K[2] 36864 | V[2] 36864 | bias 4x8960 = 109,568 B.
// ---------------------------------------------------------------------------
__global__ void __launch_bounds__(128, 2) attn_kernel(const float* __restrict__ bias_unused)
{
    extern __shared__ __align__(1024) unsigned char smatt[];
    const uint32_t smem_b = (uint32_t)__cvta_generic_to_shared(smatt);

    const int tid  = threadIdx.x;
    const int lane = tid & 31, warp = tid >> 5;
    const int q    = lane & 3, l4 = lane >> 2;
    const int g    = lane >> 3, r8 = lane & 7;
    const int b    = blockIdx.z, h = blockIdx.y;
    const int i0   = blockIdx.x << 7;
    const int W0   = warp << 5;                   // 32 rows per warp

    const __half* __restrict__ Qg = (const __half*)g_Q4 + ((size_t)(b*NH + h)*SEQ + i0)*DH;
    const __half* __restrict__ Kg = (const __half*)g_K4 + (size_t)(b*NH + h)*SEQ*DH;
    const __half* __restrict__ Vg = (const __half*)g_V4 + (size_t)(b*NH + h)*SEQ*DH;
    // warp covers i16 blocks (i0>>4)+warp*2 and +1
    const int i16g = (i0 >> 4) + warp*2;
    const __half* __restrict__ B2h = (const __half*)g_B2 + ((size_t)(h*64 + i16g) * 8) * 2048;

    const uint32_t koff = (((g>>1)*8 + r8)*72 + (g&1)*8) * 2;   // K non-trans
    const uint32_t voff = (((g&1)*8 + r8)*72 + (g>>1)*8) * 2;   // V trans
    const uint32_t bias_sm = smem_b + 73728 + warp*8960;        // own stripe, 16 rows x 560B

    // stage 128 rows of K and V (18432 B each); 128 threads, 16 cp16 each
    auto stage_kv = [&](int j0, int buf) {
        #pragma unroll
        for (int t = 0; t < 8; t++) {
            const int f = tid + t*128;                // 0..1023
            const int row = f >> 3, cB = (f & 7) * 16;
            cp16(smem_b + buf*18432 + row*144 + cB,         Kg + (size_t)(j0+row)*DH + cB/2);
            cp16(smem_b + 36864 + buf*18432 + row*144 + cB, Vg + (size_t)(j0+row)*DH + cB/2);
        }
        asm volatile("cp.async.commit_group;");
    };
    // per-warp stripe: 16 rows (2 i16-blocks x 8 l-rows) x 512B data, pitch 560B
    auto stage_bias = [&](int j0) {
        #pragma unroll
        for (int t = 0; t < 16; t++) {
            const int u = lane + 32*t;                // 0..511
            const int row = u >> 5, cB = (u & 31) * 16;
            // src row: (row>>3) selects i16 block (+8*2048 halfs), (row&7) = l
            const __half* src = B2h + (size_t)(row >> 3)*16384 + (size_t)(row & 7)*2048
                              + j0*2 + cB/2;
            cp16(bias_sm + row*560 + cB, src);
        }
        asm volatile("cp.async.commit_group;");
    };

    stage_kv(0, 0);
    stage_bias(0);

    // Q a-frags -> registers (one-time), 2 m-frags
    const uint32_t* Qu = (const uint32_t*)Qg;
    uint32_t qf[2][4][4];
    #pragma unroll
    for (int mt = 0; mt < 2; mt++)
        #pragma unroll
        for (int ks = 0; ks < 4; ks++) {
            const int r = W0 + mt*16 + l4;
            qf[mt][ks][0] = Qu[(size_t)r*32     + ks*8 + q];
            qf[mt][ks][1] = Qu[(size_t)(r+8)*32 + ks*8 + q];
            qf[mt][ks][2] = Qu[(size_t)r*32     + ks*8 + 4 + q];
            qf[mt][ks][3] = Qu[(size_t)(r+8)*32 + ks*8 + 4 + q];
        }

    float o[2][8][4] = {};
    float lpacc[2][4] = {};
    const uint32_t ONES = 0x3C003C00u;

    for (int it = 0; it < 8; it++) {
        const int j0  = it << 7;
        const int buf = it & 1;

        asm volatile("cp.async.wait_group 1;");   // KV_it resident (bias_it may fly)
        __syncthreads();                          // readers of buf^1 done

        if (it < 7) stage_kv(j0 + 128, buf ^ 1);

        #pragma unroll
        for (int sub = 0; sub < 2; sub++) {
            const uint32_t ksb = smem_b + buf*18432 + sub*9216;
            const uint32_t vsb = smem_b + 36864 + buf*18432 + sub*9216;

            // S = Q K^T  (each K ldm4 feeds 4 mmas)
            float s[2][8][4] = {};
            #pragma unroll
            for (int ks = 0; ks < 4; ks++) {
                #pragma unroll
                for (int p = 0; p < 4; p++) {
                    uint32_t b0, b1, b2, b3;
                    ldm4(b0, b1, b2, b3, ksb + koff + p*2304 + ks*32);
                    #pragma unroll
                    for (int mt = 0; mt < 2; mt++) {
                        mma16(s[mt][2*p],   qf[mt][ks][0], qf[mt][ks][1],
                              qf[mt][ks][2], qf[mt][ks][3], b0, b1);
                        mma16(s[mt][2*p+1], qf[mt][ks][0], qf[mt][ks][1],
                              qf[mt][ks][2], qf[mt][ks][3], b2, b3);
                    }
                }
            }

            if (sub == 0) {
                if (it < 7) { asm volatile("cp.async.wait_group 1;"); }
                else        { asm volatile("cp.async.wait_group 0;"); }
            }

            // P = exp2(s + bias): fp32 add, pack once, f16x2 exp
            uint32_t ph0[2][8], ph1[2][8];
            #pragma unroll
            for (int mt = 0; mt < 2; mt++)
                #pragma unroll
                for (int nt = 0; nt < 8; nt++) {
                    const uint2 bh = *(const uint2*)(smatt + 73728 + warp*8960
                                                     + (mt*8 + l4)*560 + sub*256 + nt*32 + q*8);
                    const float2 bf0 = __half22float2(*(const __half2*)&bh.x);
                    const float2 bf1 = __half22float2(*(const __half2*)&bh.y);
                    ph0[mt][nt] = hexp2_2(pack2(s[mt][nt][0] + bf0.x, s[mt][nt][1] + bf0.y));
                    ph1[mt][nt] = hexp2_2(pack2(s[mt][nt][2] + bf1.x, s[mt][nt][3] + bf1.y));
                }

            // row sums via ones-mma
            #pragma unroll
            for (int mt = 0; mt < 2; mt++)
                #pragma unroll
                for (int ks = 0; ks < 4; ks++)
                    mma16(lpacc[mt], ph0[mt][2*ks], ph1[mt][2*ks],
                          ph0[mt][2*ks+1], ph1[mt][2*ks+1], ONES, ONES);

            // O += P @ V  (each V ldm4t feeds 4 mmas)
            #pragma unroll
            for (int ks = 0; ks < 4; ks++) {
                #pragma unroll
                for (int p = 0; p < 4; p++) {
                    uint32_t b0, b1, b2, b3;
                    ldm4t(b0, b1, b2, b3, vsb + voff + ks*2304 + p*32);
                    #pragma unroll
                    for (int mt = 0; mt < 2; mt++) {
                        mma16(o[mt][2*p],   ph0[mt][2*ks], ph1[mt][2*ks],
                              ph0[mt][2*ks+1], ph1[mt][2*ks+1], b0, b1);
                        mma16(o[mt][2*p+1], ph0[mt][2*ks], ph1[mt][2*ks],
                              ph0[mt][2*ks+1], ph1[mt][2*ks+1], b2, b3);
                    }
                }
            }
        }

        if (it < 7) stage_bias(j0 + 128);
    }

    __half* __restrict__ AOh = (__half*)g_AO4;
    #pragma unroll
    for (int mt = 0; mt < 2; mt++) {
        const float inv0 = 1.f / lpacc[mt][0];
        const float inv1 = 1.f / lpacc[mt][2];
        const int gi = i0 + W0 + mt*16 + l4;
        #pragma unroll
        for (int nt = 0; nt < 8; nt++) {
            const int d = nt*8 + 2*q;
            const size_t b0 = ((size_t)b*SEQ + gi)*DIM + h*DH + d;
            const size_t b1 = ((size_t)b*SEQ + gi + 8)*DIM + h*DH + d;
            *(uint32_t*)&AOh[b0] = pack2(o[mt][nt][0]*inv0, o[mt][nt][1]*inv0);
            *(uint32_t*)&AOh[b1] = pack2(o[mt][nt][2]*inv1, o[mt][nt][3]*inv1);
        }
    }
}

// ---------------------------------------------------------------------------
extern "C" void kernel_launch(void* const* d_in, const int* in_sizes, int n_in,
                              void* d_out, int out_size)
{
    const float* x    = (const float*)d_in[0];
    const float* bias = (const float*)d_in[1];
    const float* Wq   = (const float*)d_in[2];
    const float* Wk   = (const float*)d_in[3];
    const float* Wv   = (const float*)d_in[4];
    const float* Wo   = (const float*)d_in[5];
    float* out = (float*)d_out;

    prep_all<<<8704, 256>>>(x, bias, Wq, Wk, Wv, Wo);

    const int mm_smem = 73728;   // A[2] 2x18432 | B[2] 2x18432
    cudaFuncSetAttribute(mm_kernel, cudaFuncAttributeMaxDynamicSharedMemorySize, mm_smem);
    mm_kernel<<<dim3(DIM/128, (NB*SEQ)/128, 3), 128, mm_smem>>>(nullptr, 0);

    const int at_smem = 109568;  // K 2x18432 | V 2x18432 | bias 4x8960
    cudaFuncSetAttribute(attn_kernel, cudaFuncAttributeMaxDynamicSharedMemorySize, at_smem);
    attn_kernel<<<dim3(SEQ/128, NH, NB), 128, at_smem>>>(bias);

    mm_kernel<<<dim3(DIM/128, (NB*SEQ)/128, 1), 128, mm_smem>>>(out, 1);
}

// round 16
// speedup vs baseline: 1.0438x; 1.0267x over previous
#include <cuda_runtime.h>
#include <cuda_fp16.h>
#include <cstdint>

#define NB   16
#define SEQ  1024
#define DIM  512
#define NH   8
#define DH   64

// Scratch (allocation-free __device__ globals)
__device__ uint4 g_Q4 [(size_t)NB*NH*SEQ*DH/8];   // Q fp16 [b,h,i,d] (pre-scaled 0.125*log2e)
__device__ uint4 g_K4 [(size_t)NB*NH*SEQ*DH/8];   // K fp16 [b,h,i,d]
__device__ uint4 g_V4 [(size_t)NB*NH*SEQ*DH/8];   // V fp16 [b,h,i,d]
__device__ uint4 g_AO4[(size_t)NB*SEQ*DIM/8];     // attn out fp16
__device__ uint4 g_X4 [(size_t)NB*SEQ*DIM/8];     // x fp16
__device__ uint4 g_W4 [(size_t)4*DIM*DIM/8];      // Wq|Wk|Wv|Wo fp16
// bias fp16 * log2e, permuted (see prep fused kernel)
__device__ uint4 g_B2 [(size_t)NH*SEQ*SEQ/8];

#define LOG2E 1.4426950408889634f

__device__ __forceinline__ uint32_t pack2(float a, float b) {
    __half2 h = __floats2half2_rn(a, b);
    return *(uint32_t*)&h;
}

__device__ __forceinline__ void mma16(float c[4], uint32_t a0, uint32_t a1,
                                      uint32_t a2, uint32_t a3,
                                      uint32_t b0, uint32_t b1) {
    asm volatile(
        "mma.sync.aligned.m16n8k16.row.col.f32.f16.f16.f32 "
        "{%0,%1,%2,%3}, {%4,%5,%6,%7}, {%8,%9}, {%0,%1,%2,%3};"
        : "+f"(c[0]), "+f"(c[1]), "+f"(c[2]), "+f"(c[3])
        : "r"(a0), "r"(a1), "r"(a2), "r"(a3), "r"(b0), "r"(b1));
}

__device__ __forceinline__ void ldm4(uint32_t& r0, uint32_t& r1, uint32_t& r2,
                                     uint32_t& r3, uint32_t addr) {
    asm volatile("ldmatrix.sync.aligned.m8n8.x4.shared.b16 {%0,%1,%2,%3}, [%4];"
                 : "=r"(r0), "=r"(r1), "=r"(r2), "=r"(r3) : "r"(addr));
}
__device__ __forceinline__ void ldm4t(uint32_t& r0, uint32_t& r1, uint32_t& r2,
                                      uint32_t& r3, uint32_t addr) {
    asm volatile("ldmatrix.sync.aligned.m8n8.x4.trans.shared.b16 {%0,%1,%2,%3}, [%4];"
                 : "=r"(r0), "=r"(r1), "=r"(r2), "=r"(r3) : "r"(addr));
}

__device__ __forceinline__ void cp16(uint32_t dst, const void* src) {
    asm volatile("cp.async.cg.shared.global [%0], [%1], 16;" :: "r"(dst), "l"(src));
}

__device__ __forceinline__ uint32_t hexp2_2(uint32_t a) {
    uint32_t r;
    asm("ex2.approx.f16x2 %0, %1;" : "=r"(r) : "r"(a));
    return r;
}

// ---------------------------------------------------------------------------
// Fused prep: fp32 -> fp16 for x / W / bias (one launch).
// ---------------------------------------------------------------------------
__global__ void __launch_bounds__(256) prep_all(
    const float* __restrict__ X,  const float* __restrict__ B,
    const float* __restrict__ Wq, const float* __restrict__ Wk,
    const float* __restrict__ Wv, const float* __restrict__ Wo)
{
    const int bx = blockIdx.x;
    if (bx < 4096) {
        const size_t i = ((size_t)bx*256 + threadIdx.x) * 8;
        const float4 f0 = *(const float4*)&X[i];
        const float4 f1 = *(const float4*)&X[i+4];
        g_X4[i >> 3] = make_uint4(pack2(f0.x, f0.y), pack2(f0.z, f0.w),
                                  pack2(f1.x, f1.y), pack2(f1.z, f1.w));
    } else if (bx < 4608) {
        const size_t i = ((size_t)(bx-4096)*256 + threadIdx.x) * 8;
        const int w = (int)(i >> 18);
        const float* __restrict__ src = (w==0)?Wq:(w==1)?Wk:(w==2)?Wv:Wo;
        const size_t p = i & ((1u << 18) - 1);
        const float4 f0 = *(const float4*)&src[p];
        const float4 f1 = *(const float4*)&src[p+4];
        g_W4[i >> 3] = make_uint4(pack2(f0.x, f0.y), pack2(f0.z, f0.w),
                                  pack2(f1.x, f1.y), pack2(f1.z, f1.w));
    } else {
        const size_t t = (size_t)(bx-4608)*256 + threadIdx.x;   // 0 .. 1M-1
        const size_t L = t * 8;
        const int R   = (int)(L >> 11);
        const int o   = (int)(L & 2047);
        const int h   = R >> 9;
        const int rem = R & 511;
        const int i16 = rem >> 3, l = rem & 7;
        const int bi  = i16*16 + l;
        const float* __restrict__ Bh = B + ((size_t)h << 20);

        uint32_t out[4];
        #pragma unroll
        for (int g2 = 0; g2 < 2; g2++) {
            const int j = ((o >> 2) + g2) * 2;
            const float2 f0 = *(const float2*)&Bh[(size_t)bi*SEQ + j];
            const float2 f1 = *(const float2*)&Bh[(size_t)(bi+8)*SEQ + j];
            out[g2*2 + 0] = pack2(f0.x*LOG2E, f0.y*LOG2E);
            out[g2*2 + 1] = pack2(f1.x*LOG2E, f1.y*LOG2E);
        }
        g_B2[t] = make_uint4(out[0], out[1], out[2], out[3]);
    }
}

// ---------------------------------------------------------------------------
// GEMM (qkv + oproj): Y = A @ W^T, fp16 in, fp32 accum, mma.sync.
// BM=128, BN=128, BK=64; 256 threads = 8 warps (4m x 2n), WARP TILE 32x64
// (R11 shape: ~120 regs -> 2 CTAs/SM = 16 warps/SM, double the latency hiding
// of the 64x64-tile variant that flat-lined at occ 11%/issue 15%).
// smem pitch 72 halfs; A[2] @ 0/18432, B[2] @ 36864/55296 = 73,728 B.
// ---------------------------------------------------------------------------
__global__ void __launch_bounds__(256, 2) mm_kernel(float* __restrict__ outp, int op)
{
    extern __shared__ __align__(1024) unsigned char smraw[];
    const uint32_t smem_b = (uint32_t)__cvta_generic_to_shared(smraw);

    const int z = op ? 3 : blockIdx.z;
    const __half* __restrict__ At = op ? (const __half*)g_AO4 : (const __half*)g_X4;
    const __half* __restrict__ Bt = (const __half*)g_W4 + (size_t)z*DIM*DIM;

    const int tid  = threadIdx.x;
    const int lane = tid & 31, warp = tid >> 5;
    const int q    = lane & 3, l4 = lane >> 2;
    const int g    = lane >> 3, r8 = lane & 7;
    const int wm   = warp >> 1, wn = warp & 1;
    const int m0   = blockIdx.y << 7;
    const int c0   = blockIdx.x << 7;

    // ldmatrix per-lane byte offsets (pitch 144 B)
    const uint32_t aoff = ((wm*32 + (g&1)*8 + r8)*72 + (g>>1)*8) * 2;
    const uint32_t boff = ((wn*64 + (g>>1)*8 + r8)*72 + (g&1)*8) * 2;

    auto stage = [&](int k0, int buf) {
        #pragma unroll
        for (int t = 0; t < 8; t++) {
            const int f = tid + t*256;                   // 0..2047 (A then B)
            const int r = (f >> 3) & 127;
            const int j = f & 7;
            const uint32_t dst = smem_b + ((f & 1024) ? 36864 : 0) + buf*18432
                               + r*144 + j*16;
            const __half* src = ((f & 1024) ? Bt + (size_t)(c0+r)*DIM
                                            : At + (size_t)(m0+r)*DIM) + k0 + j*8;
            cp16(dst, src);
        }
        asm volatile("cp.async.commit_group;");
    };

    float acc[2][8][4] = {};
    stage(0, 0);

    for (int kt = 0; kt < 8; kt++) {
        asm volatile("cp.async.wait_group 0;");
        __syncthreads();
        if (kt < 7) stage((kt+1)*64, (kt+1) & 1);

        const uint32_t As_b = smem_b + (kt & 1)*18432;
        const uint32_t Bs_b = smem_b + 36864 + (kt & 1)*18432;

        #pragma unroll
        for (int ks = 0; ks < 4; ks++) {
            uint32_t a[2][4];
            #pragma unroll
            for (int mt = 0; mt < 2; mt++)
                ldm4(a[mt][0], a[mt][1], a[mt][2], a[mt][3],
                     As_b + aoff + mt*2304 + ks*32);
            #pragma unroll
            for (int p = 0; p < 4; p++) {
                uint32_t b0, b1, b2, b3;
                ldm4(b0, b1, b2, b3, Bs_b + boff + p*2304 + ks*32);
                mma16(acc[0][2*p],   a[0][0], a[0][1], a[0][2], a[0][3], b0, b1);
                mma16(acc[1][2*p],   a[1][0], a[1][1], a[1][2], a[1][3], b0, b1);
                mma16(acc[0][2*p+1], a[0][0], a[0][1], a[0][2], a[0][3], b2, b3);
                mma16(acc[1][2*p+1], a[1][0], a[1][1], a[1][2], a[1][3], b2, b3);
            }
        }
    }

    if (op) {
        #pragma unroll
        for (int mt = 0; mt < 2; mt++)
            #pragma unroll
            for (int half = 0; half < 2; half++) {
                const int m = m0 + wm*32 + mt*16 + half*8 + l4;
                #pragma unroll
                for (int nt = 0; nt < 8; nt++) {
                    const int col = c0 + wn*64 + nt*8 + 2*q;
                    *(float2*)&outp[(size_t)m*DIM + col] =
                        make_float2(acc[mt][nt][half*2], acc[mt][nt][half*2+1]);
                }
            }
    } else {
        __half* __restrict__ Y = (__half*)((z==0) ? g_Q4 : (z==1) ? g_K4 : g_V4);
        const float scale = (z == 0) ? 0.125f * LOG2E : 1.0f;
        #pragma unroll
        for (int mt = 0; mt < 2; mt++)
            #pragma unroll
            for (int half = 0; half < 2; half++) {
                const int m  = m0 + wm*32 + mt*16 + half*8 + l4;
                const int bb = m >> 10, i = m & (SEQ-1);
                #pragma unroll
                for (int nt = 0; nt < 8; nt++) {
                    const int col = c0 + wn*64 + nt*8 + 2*q;
                    const int h = col >> 6, d = col & 63;
                    const size_t base = ((size_t)(bb*NH + h)*SEQ + i)*DH + d;
                    *(uint32_t*)&Y[base] = pack2(acc[mt][nt][half*2]   * scale,
                                                 acc[mt][nt][half*2+1] * scale);
                }
            }
    }
}

// ---------------------------------------------------------------------------
// Flash attention (unchanged from R15, 246.5us-passing version).
// 128 thr = 4 warps x 32 q-rows; KV tiles of 128 keys, double-buffered.
// ---------------------------------------------------------------------------
__global__ void __launch_bounds__(128, 2) attn_kernel(const float* __restrict__ bias_unused)
{
    extern __shared__ __align__(1024) unsigned char smatt[];
    const uint32_t smem_b = (uint32_t)__cvta_generic_to_shared(smatt);

    const int tid  = threadIdx.x;
    const int lane = tid & 31, warp = tid >> 5;
    const int q    = lane & 3, l4 = lane >> 2;
    const int g    = lane >> 3, r8 = lane & 7;
    const int b    = blockIdx.z, h = blockIdx.y;
    const int i0   = blockIdx.x << 7;
    const int W0   = warp << 5;                   // 32 rows per warp

    const __half* __restrict__ Qg = (const __half*)g_Q4 + ((size_t)(b*NH + h)*SEQ + i0)*DH;
    const __half* __restrict__ Kg = (const __half*)g_K4 + (size_t)(b*NH + h)*SEQ*DH;
    const __half* __restrict__ Vg = (const __half*)g_V4 + (size_t)(b*NH + h)*SEQ*DH;
    const int i16g = (i0 >> 4) + warp*2;
    const __half* __restrict__ B2h = (const __half*)g_B2 + ((size_t)(h*64 + i16g) * 8) * 2048;

    const uint32_t koff = (((g>>1)*8 + r8)*72 + (g&1)*8) * 2;   // K non-trans
    const uint32_t voff = (((g&1)*8 + r8)*72 + (g>>1)*8) * 2;   // V trans
    const uint32_t bias_sm = smem_b + 73728 + warp*8960;        // own stripe, 16 rows x 560B

    auto stage_kv = [&](int j0, int buf) {
        #pragma unroll
        for (int t = 0; t < 8; t++) {
            const int f = tid + t*128;                // 0..1023
            const int row = f >> 3, cB = (f & 7) * 16;
            cp16(smem_b + buf*18432 + row*144 + cB,         Kg + (size_t)(j0+row)*DH + cB/2);
            cp16(smem_b + 36864 + buf*18432 + row*144 + cB, Vg + (size_t)(j0+row)*DH + cB/2);
        }
        asm volatile("cp.async.commit_group;");
    };
    auto stage_bias = [&](int j0) {
        #pragma unroll
        for (int t = 0; t < 16; t++) {
            const int u = lane + 32*t;                // 0..511
            const int row = u >> 5, cB = (u & 31) * 16;
            const __half* src = B2h + (size_t)(row >> 3)*16384 + (size_t)(row & 7)*2048
                              + j0*2 + cB/2;
            cp16(bias_sm + row*560 + cB, src);
        }
        asm volatile("cp.async.commit_group;");
    };

    stage_kv(0, 0);
    stage_bias(0);

    const uint32_t* Qu = (const uint32_t*)Qg;
    uint32_t qf[2][4][4];
    #pragma unroll
    for (int mt = 0; mt < 2; mt++)
        #pragma unroll
        for (int ks = 0; ks < 4; ks++) {
            const int r = W0 + mt*16 + l4;
            qf[mt][ks][0] = Qu[(size_t)r*32     + ks*8 + q];
            qf[mt][ks][1] = Qu[(size_t)(r+8)*32 + ks*8 + q];
            qf[mt][ks][2] = Qu[(size_t)r*32     + ks*8 + 4 + q];
            qf[mt][ks][3] = Qu[(size_t)(r+8)*32 + ks*8 + 4 + q];
        }

    float o[2][8][4] = {};
    float lpacc[2][4] = {};
    const uint32_t ONES = 0x3C003C00u;

    for (int it = 0; it < 8; it++) {
        const int j0  = it << 7;
        const int buf = it & 1;

        asm volatile("cp.async.wait_group 1;");   // KV_it resident (bias_it may fly)
        __syncthreads();                          // readers of buf^1 done

        if (it < 7) stage_kv(j0 + 128, buf ^ 1);

        #pragma unroll
        for (int sub = 0; sub < 2; sub++) {
            const uint32_t ksb = smem_b + buf*18432 + sub*9216;
            const uint32_t vsb = smem_b + 36864 + buf*18432 + sub*9216;

            float s[2][8][4] = {};
            #pragma unroll
            for (int ks = 0; ks < 4; ks++) {
                #pragma unroll
                for (int p = 0; p < 4; p++) {
                    uint32_t b0, b1, b2, b3;
                    ldm4(b0, b1, b2, b3, ksb + koff + p*2304 + ks*32);
                    #pragma unroll
                    for (int mt = 0; mt < 2; mt++) {
                        mma16(s[mt][2*p],   qf[mt][ks][0], qf[mt][ks][1],
                              qf[mt][ks][2], qf[mt][ks][3], b0, b1);
                        mma16(s[mt][2*p+1], qf[mt][ks][0], qf[mt][ks][1],
                              qf[mt][ks][2], qf[mt][ks][3], b2, b3);
                    }
                }
            }

            if (sub == 0) {
                if (it < 7) { asm volatile("cp.async.wait_group 1;"); }
                else        { asm volatile("cp.async.wait_group 0;"); }
            }

            uint32_t ph0[2][8], ph1[2][8];
            #pragma unroll
            for (int mt = 0; mt < 2; mt++)
                #pragma unroll
                for (int nt = 0; nt < 8; nt++) {
                    const uint2 bh = *(const uint2*)(smatt + 73728 + warp*8960
                                                     + (mt*8 + l4)*560 + sub*256 + nt*32 + q*8);
                    const float2 bf0 = __half22float2(*(const __half2*)&bh.x);
                    const float2 bf1 = __half22float2(*(const __half2*)&bh.y);
                    ph0[mt][nt] = hexp2_2(pack2(s[mt][nt][0] + bf0.x, s[mt][nt][1] + bf0.y));
                    ph1[mt][nt] = hexp2_2(pack2(s[mt][nt][2] + bf1.x, s[mt][nt][3] + bf1.y));
                }

            #pragma unroll
            for (int mt = 0; mt < 2; mt++)
                #pragma unroll
                for (int ks = 0; ks < 4; ks++)
                    mma16(lpacc[mt], ph0[mt][2*ks], ph1[mt][2*ks],
                          ph0[mt][2*ks+1], ph1[mt][2*ks+1], ONES, ONES);

            #pragma unroll
            for (int ks = 0; ks < 4; ks++) {
                #pragma unroll
                for (int p = 0; p < 4; p++) {
                    uint32_t b0, b1, b2, b3;
                    ldm4t(b0, b1, b2, b3, vsb + voff + ks*2304 + p*32);
                    #pragma unroll
                    for (int mt = 0; mt < 2; mt++) {
                        mma16(o[mt][2*p],   ph0[mt][2*ks], ph1[mt][2*ks],
                              ph0[mt][2*ks+1], ph1[mt][2*ks+1], b0, b1);
                        mma16(o[mt][2*p+1], ph0[mt][2*ks], ph1[mt][2*ks],
                              ph0[mt][2*ks+1], ph1[mt][2*ks+1], b2, b3);
                    }
                }
            }
        }

        if (it < 7) stage_bias(j0 + 128);
    }

    __half* __restrict__ AOh = (__half*)g_AO4;
    #pragma unroll
    for (int mt = 0; mt < 2; mt++) {
        const float inv0 = 1.f / lpacc[mt][0];
        const float inv1 = 1.f / lpacc[mt][2];
        const int gi = i0 + W0 + mt*16 + l4;
        #pragma unroll
        for (int nt = 0; nt < 8; nt++) {
            const int d = nt*8 + 2*q;
            const size_t b0 = ((size_t)b*SEQ + gi)*DIM + h*DH + d;
            const size_t b1 = ((size_t)b*SEQ + gi + 8)*DIM + h*DH + d;
            *(uint32_t*)&AOh[b0] = pack2(o[mt][nt][0]*inv0, o[mt][nt][1]*inv0);
            *(uint32_t*)&AOh[b1] = pack2(o[mt][nt][2]*inv1, o[mt][nt][3]*inv1);
        }
    }
}

// ---------------------------------------------------------------------------
extern "C" void kernel_launch(void* const* d_in, const int* in_sizes, int n_in,
                              void* d_out, int out_size)
{
    const float* x    = (const float*)d_in[0];
    const float* bias = (const float*)d_in[1];
    const float* Wq   = (const float*)d_in[2];
    const float* Wk   = (const float*)d_in[3];
    const float* Wv   = (const float*)d_in[4];
    const float* Wo   = (const float*)d_in[5];
    float* out = (float*)d_out;

    prep_all<<<8704, 256>>>(x, bias, Wq, Wk, Wv, Wo);

    const int mm_smem = 73728;   // A[2] 2x18432 | B[2] 2x18432
    cudaFuncSetAttribute(mm_kernel, cudaFuncAttributeMaxDynamicSharedMemorySize, mm_smem);
    mm_kernel<<<dim3(DIM/128, (NB*SEQ)/128, 3), 256, mm_smem>>>(nullptr, 0);

    const int at_smem = 109568;  // K 2x18432 | V 2x18432 | bias 4x8960
    cudaFuncSetAttribute(attn_kernel, cudaFuncAttributeMaxDynamicSharedMemorySize, at_smem);
    attn_kernel<<<dim3(SEQ/128, NH, NB), 128, at_smem>>>(bias);

    mm_kernel<<<dim3(DIM/128, (NB*SEQ)/128, 1), 256, mm_smem>>>(out, 1);
}